// round 2
// baseline (speedup 1.0000x reference)
#include <cuda_runtime.h>

#define B_SZ  2
#define S_LEN 2048
#define D_IN  1024
#define NH    16
#define DKH   64

typedef unsigned long long u64;

// Scratch (allocation-free rule: __device__ globals). 4 x 16MB.
__device__ float g_Q[B_SZ * NH * S_LEN * DKH];
__device__ float g_K[B_SZ * NH * S_LEN * DKH];
__device__ float g_V[B_SZ * NH * S_LEN * DKH];
__device__ float g_O[B_SZ * NH * S_LEN * DKH];

// ---- packed f32x2 helpers (Blackwell double-rate fp32 path) ----
__device__ __forceinline__ u64 ffma2(u64 a, u64 b, u64 c) {
    u64 d; asm("fma.rn.f32x2 %0, %1, %2, %3;" : "=l"(d) : "l"(a), "l"(b), "l"(c)); return d;
}
__device__ __forceinline__ u64 fmul2(u64 a, u64 b) {
    u64 d; asm("mul.rn.f32x2 %0, %1, %2;" : "=l"(d) : "l"(a), "l"(b)); return d;
}
__device__ __forceinline__ u64 fpack2(float lo, float hi) {
    u64 d; asm("mov.b64 %0, {%1, %2};" : "=l"(d) : "f"(lo), "f"(hi)); return d;
}
__device__ __forceinline__ void funpack2(u64 d, float& lo, float& hi) {
    asm("mov.b64 {%0, %1}, %2;" : "=f"(lo), "=f"(hi) : "l"(d));
}

// ============================================================================
// Kernel 1: fused QKV projection.
// For each (b, h, qkv): [64 x 1024] x [1024 x 64] tile GEMM.
// grid = (S/64, B*H, 3), block = 256 (16x16, each thread 4x4 outputs).
// ============================================================================
__global__ __launch_bounds__(256) void qkv_proj_kernel(
    const float* __restrict__ qin, const float* __restrict__ kin, const float* __restrict__ vin,
    const float* __restrict__ Wq, const float* __restrict__ bq,
    const float* __restrict__ Wk, const float* __restrict__ bk,
    const float* __restrict__ Wv, const float* __restrict__ bv)
{
    const int stile = blockIdx.x;
    const int bh    = blockIdx.y;
    const int which = blockIdx.z;
    const int b = bh >> 4, h = bh & 15;

    const float* X; const float* W; const float* bias; float* Out;
    if (which == 0)      { X = qin; W = Wq; bias = bq; Out = g_Q; }
    else if (which == 1) { X = kin; W = Wk; bias = bk; Out = g_K; }
    else                 { X = vin; W = Wv; bias = bv; Out = g_V; }

    X    += (size_t)b * S_LEN * D_IN + (size_t)stile * 64 * D_IN;
    W    += (size_t)h * D_IN * DKH;
    bias += h * DKH;
    Out  += ((size_t)bh * S_LEN + (size_t)stile * 64) * DKH;

    __shared__ __align__(16) float As[16][68];  // As[k][m], padded
    __shared__ __align__(16) float Bs[16][64];  // Bs[k][n]

    const int tid  = threadIdx.x;
    const int tx   = tid & 15, ty = tid >> 4;
    const int arow = tid >> 2, acol = (tid & 3) << 2;
    const int brow = tid >> 4, bcol = (tid & 15) << 2;

    u64 acc[4][2] = {};

    for (int k0 = 0; k0 < D_IN; k0 += 16) {
        float4 av  = *(const float4*)(X + (size_t)arow * D_IN + k0 + acol);
        float4 bv4 = *(const float4*)(W + (size_t)(k0 + brow) * DKH + bcol);
        __syncthreads();
        As[acol + 0][arow] = av.x;
        As[acol + 1][arow] = av.y;
        As[acol + 2][arow] = av.z;
        As[acol + 3][arow] = av.w;
        *(float4*)&Bs[brow][bcol] = bv4;
        __syncthreads();
        #pragma unroll
        for (int kk = 0; kk < 16; kk++) {
            float4 a = *(const float4*)&As[kk][ty << 2];
            ulonglong2 bb2 = *(const ulonglong2*)&Bs[kk][tx << 2];
            u64 a0 = fpack2(a.x, a.x);
            u64 a1 = fpack2(a.y, a.y);
            u64 a2 = fpack2(a.z, a.z);
            u64 a3 = fpack2(a.w, a.w);
            acc[0][0] = ffma2(a0, bb2.x, acc[0][0]); acc[0][1] = ffma2(a0, bb2.y, acc[0][1]);
            acc[1][0] = ffma2(a1, bb2.x, acc[1][0]); acc[1][1] = ffma2(a1, bb2.y, acc[1][1]);
            acc[2][0] = ffma2(a2, bb2.x, acc[2][0]); acc[2][1] = ffma2(a2, bb2.y, acc[2][1]);
            acc[3][0] = ffma2(a3, bb2.x, acc[3][0]); acc[3][1] = ffma2(a3, bb2.y, acc[3][1]);
        }
    }

    float4 bb = *(const float4*)(bias + (tx << 2));
    #pragma unroll
    for (int i = 0; i < 4; i++) {
        float r0, r1, r2, r3;
        funpack2(acc[i][0], r0, r1);
        funpack2(acc[i][1], r2, r3);
        float4 o = make_float4(r0 + bb.x, r1 + bb.y, r2 + bb.z, r3 + bb.w);
        *(float4*)(Out + (size_t)((ty << 2) + i) * DKH + (tx << 2)) = o;
    }
}

// ============================================================================
// Kernel 2: flash attention (non-causal, full softmax).
// One thread owns one query row (q + acc in packed-f32x2 registers).
// grid = (S/64, B*H), block = 64. K/V tiles 64x64 in smem.
// ============================================================================
__global__ __launch_bounds__(64) void attn_kernel()
{
    const int bh  = blockIdx.y;
    const int tid = threadIdx.x;
    const size_t base = (size_t)bh * S_LEN * DKH;
    const int row = blockIdx.x * 64 + tid;

    __shared__ __align__(16) float Ks[64 * DKH];
    __shared__ __align__(16) float Vs[64 * DKH];

    u64 q2[32];
    {
        const ulonglong2* qsrc = (const ulonglong2*)(g_Q + base + (size_t)row * DKH);
        #pragma unroll
        for (int i = 0; i < 16; i++) { ulonglong2 v = qsrc[i]; q2[2*i] = v.x; q2[2*i+1] = v.y; }
    }

    u64 acc[32] = {};
    float m = -3.0e38f, l = 0.f;

    for (int t = 0; t < S_LEN; t += 64) {
        __syncthreads();
        {
            const float4* ks = (const float4*)(g_K + base + (size_t)t * DKH);
            const float4* vs = (const float4*)(g_V + base + (size_t)t * DKH);
            float4* kd = (float4*)Ks;
            float4* vd = (float4*)Vs;
            #pragma unroll
            for (int i = 0; i < 16; i++) {
                kd[tid + 64 * i] = ks[tid + 64 * i];
                vd[tid + 64 * i] = vs[tid + 64 * i];
            }
        }
        __syncthreads();

        #pragma unroll 1
        for (int c = 0; c < 64; c += 8) {
            const u64* K2 = (const u64*)(Ks + c * DKH);
            const u64* V2 = (const u64*)(Vs + c * DKH);

            // scores for 8 keys: packed dot products
            u64 s2[8] = {};
            #pragma unroll
            for (int d = 0; d < 32; d += 2) {
                u64 qa = q2[d], qb = q2[d + 1];
                #pragma unroll
                for (int j = 0; j < 8; j++) {
                    ulonglong2 kk = *(const ulonglong2*)(K2 + j * 32 + d);
                    s2[j] = ffma2(qb, kk.y, ffma2(qa, kk.x, s2[j]));
                }
            }
            float sc[8];
            float cmax = -3.0e38f;
            #pragma unroll
            for (int j = 0; j < 8; j++) {
                float lo, hi; funpack2(s2[j], lo, hi);
                sc[j] = (lo + hi) * 0.125f;       // 1/sqrt(64)
                cmax = fmaxf(cmax, sc[j]);
            }
            float mnew = fmaxf(m, cmax);
            float corr = __expf(m - mnew);
            float p[8]; float psum = 0.f;
            #pragma unroll
            for (int j = 0; j < 8; j++) { p[j] = __expf(sc[j] - mnew); psum += p[j]; }
            l = l * corr + psum;
            m = mnew;
            u64 corr2 = fpack2(corr, corr);
            #pragma unroll
            for (int d = 0; d < 32; d++) acc[d] = fmul2(acc[d], corr2);

            #pragma unroll
            for (int j = 0; j < 8; j++) {
                u64 pj = fpack2(p[j], p[j]);
                #pragma unroll
                for (int d = 0; d < 32; d += 2) {
                    ulonglong2 vv = *(const ulonglong2*)(V2 + j * 32 + d);
                    acc[d]     = ffma2(pj, vv.x, acc[d]);
                    acc[d + 1] = ffma2(pj, vv.y, acc[d + 1]);
                }
            }
        }
    }

    const float inv = 1.f / l;
    const u64 inv2 = fpack2(inv, inv);
    u64* orow = (u64*)(g_O + base + (size_t)row * DKH);
    #pragma unroll
    for (int d = 0; d < 32; d++) orow[d] = fmul2(acc[d], inv2);
}

// ============================================================================
// Kernel 3: output projection. [4096 x 1024] x [1024 x 1024] + bo.
// A rows gathered from g_O ([B,H,S,64] layout -> concat-head columns).
// grid = (1024/64, 4096/64), block = 256.
// ============================================================================
__global__ __launch_bounds__(256) void out_proj_kernel(
    const float* __restrict__ Wo, const float* __restrict__ bo, float* __restrict__ out)
{
    const int nt = blockIdx.x;   // 16 column tiles
    const int mt = blockIdx.y;   // 64 row tiles
    const int tid  = threadIdx.x;
    const int tx   = tid & 15, ty = tid >> 4;
    const int arow = tid >> 2, acol = (tid & 3) << 2;
    const int brow = tid >> 4, bcol = (tid & 15) << 2;

    const int r = mt * 64 + arow;     // global (b,s) row for A loads
    const int b = r >> 11, s = r & 2047;

    __shared__ __align__(16) float As[16][68];
    __shared__ __align__(16) float Bs[16][64];

    u64 acc[4][2] = {};

    for (int k0 = 0; k0 < NH * DKH; k0 += 16) {
        const int h  = k0 >> 6;
        const int kc = (k0 & 63) + acol;   // BK=16 stays within one head
        float4 av  = *(const float4*)(g_O + (((size_t)(b * NH + h) * S_LEN + s) * DKH + kc));
        float4 bv4 = *(const float4*)(Wo + (size_t)(k0 + brow) * D_IN + nt * 64 + bcol);
        __syncthreads();
        As[acol + 0][arow] = av.x;
        As[acol + 1][arow] = av.y;
        As[acol + 2][arow] = av.z;
        As[acol + 3][arow] = av.w;
        *(float4*)&Bs[brow][bcol] = bv4;
        __syncthreads();
        #pragma unroll
        for (int kk = 0; kk < 16; kk++) {
            float4 a = *(const float4*)&As[kk][ty << 2];
            ulonglong2 bb2 = *(const ulonglong2*)&Bs[kk][tx << 2];
            u64 a0 = fpack2(a.x, a.x);
            u64 a1 = fpack2(a.y, a.y);
            u64 a2 = fpack2(a.z, a.z);
            u64 a3 = fpack2(a.w, a.w);
            acc[0][0] = ffma2(a0, bb2.x, acc[0][0]); acc[0][1] = ffma2(a0, bb2.y, acc[0][1]);
            acc[1][0] = ffma2(a1, bb2.x, acc[1][0]); acc[1][1] = ffma2(a1, bb2.y, acc[1][1]);
            acc[2][0] = ffma2(a2, bb2.x, acc[2][0]); acc[2][1] = ffma2(a2, bb2.y, acc[2][1]);
            acc[3][0] = ffma2(a3, bb2.x, acc[3][0]); acc[3][1] = ffma2(a3, bb2.y, acc[3][1]);
        }
    }

    float4 bb = *(const float4*)(bo + nt * 64 + (tx << 2));
    #pragma unroll
    for (int i = 0; i < 4; i++) {
        float r0, r1, r2, r3;
        funpack2(acc[i][0], r0, r1);
        funpack2(acc[i][1], r2, r3);
        float4 o = make_float4(r0 + bb.x, r1 + bb.y, r2 + bb.z, r3 + bb.w);
        *(float4*)(out + (size_t)(mt * 64 + (ty << 2) + i) * D_IN + nt * 64 + (tx << 2)) = o;
    }
}

// ============================================================================
extern "C" void kernel_launch(void* const* d_in, const int* in_sizes, int n_in,
                              void* d_out, int out_size)
{
    (void)in_sizes; (void)n_in; (void)out_size;
    const float* query = (const float*)d_in[0];
    const float* key   = (const float*)d_in[1];
    const float* value = (const float*)d_in[2];
    const float* Wq = (const float*)d_in[3];
    const float* bq = (const float*)d_in[4];
    const float* Wk = (const float*)d_in[5];
    const float* bk = (const float*)d_in[6];
    const float* Wv = (const float*)d_in[7];
    const float* bv = (const float*)d_in[8];
    const float* Wo = (const float*)d_in[9];
    const float* bo = (const float*)d_in[10];

    dim3 g1(S_LEN / 64, B_SZ * NH, 3);
    qkv_proj_kernel<<<g1, 256>>>(query, key, value, Wq, bq, Wk, bk, Wv, bv);

    dim3 g2(S_LEN / 64, B_SZ * NH);
    attn_kernel<<<g2, 64>>>();

    dim3 g3(D_IN / 64, (B_SZ * S_LEN) / 64);
    out_proj_kernel<<<g3, 256>>>(Wo, bo, (float*)d_out);
}

// round 4
// speedup vs baseline: 5.4244x; 5.4244x over previous
#include <cuda_runtime.h>
#include <cstdint>

#define B_SZ  2
#define S_LEN 2048
#define D_IN  1024
#define NH    16
#define DKH   64

// Scratch (allocation-free rule: __device__ globals). 4 x 16MB.
__device__ float g_Q[B_SZ * NH * S_LEN * DKH];
__device__ float g_K[B_SZ * NH * S_LEN * DKH];
__device__ float g_V[B_SZ * NH * S_LEN * DKH];
__device__ float g_O[B_SZ * NH * S_LEN * DKH];

__device__ __forceinline__ uint32_t cvt_rna_tf32(float f) {
    uint32_t o; asm("cvt.rna.tf32.f32 %0, %1;" : "=r"(o) : "f"(f)); return o;
}

// mma.sync m16n8k8 tf32 (sm_80+, arch-portable — no "a" features)
__device__ __forceinline__ void mma_tf32(float d[4], const uint32_t a[4], const uint32_t b[2]) {
    asm volatile(
        "mma.sync.aligned.m16n8k8.row.col.f32.tf32.tf32.f32 "
        "{%0,%1,%2,%3}, {%4,%5,%6,%7}, {%8,%9}, {%0,%1,%2,%3};"
        : "+f"(d[0]), "+f"(d[1]), "+f"(d[2]), "+f"(d[3])
        : "r"(a[0]), "r"(a[1]), "r"(a[2]), "r"(a[3]), "r"(b[0]), "r"(b[1]));
}

// ============================================================================
// Kernel 1: fused QKV projection on tensor cores.
// C[128 x 64] = X[128 x 1024] * W[1024 x 64] + bias, per (stile, b, h, which).
// 256 threads = 8 warps (4m x 2n); warp tile 32x32; K chunk 32.
// ============================================================================
__global__ __launch_bounds__(256) void qkv_proj_kernel(
    const float* __restrict__ qin, const float* __restrict__ kin, const float* __restrict__ vin,
    const float* __restrict__ Wq, const float* __restrict__ bq,
    const float* __restrict__ Wk, const float* __restrict__ bk,
    const float* __restrict__ Wv, const float* __restrict__ bv)
{
    const int stile = blockIdx.x;
    const int bh    = blockIdx.y;
    const int which = blockIdx.z;
    const int b = bh >> 4, h = bh & 15;

    const float* X; const float* W; const float* bias; float* Out;
    if (which == 0)      { X = qin; W = Wq; bias = bq; Out = g_Q; }
    else if (which == 1) { X = kin; W = Wk; bias = bk; Out = g_K; }
    else                 { X = vin; W = Wv; bias = bv; Out = g_V; }

    X    += (size_t)b * S_LEN * D_IN + (size_t)stile * 128 * D_IN;
    W    += (size_t)h * D_IN * DKH;
    bias += h * DKH;
    Out  += ((size_t)bh * S_LEN + (size_t)stile * 128) * DKH;

    __shared__ uint32_t As[128][36];   // [m][k], pad 36 -> conflict-free frags
    __shared__ uint32_t Bs[32][72];    // [k][n], pad 72 -> conflict-free frags

    const int tid = threadIdx.x;
    const int wid = tid >> 5, lane = tid & 31;
    const int g = lane >> 2, tg = lane & 3;
    const int wm = (wid >> 1) * 32;    // warp m offset
    const int wn = (wid & 1) * 32;     // warp n offset

    float acc[2][4][4];
    #pragma unroll
    for (int i = 0; i < 2; i++)
        #pragma unroll
        for (int j = 0; j < 4; j++)
            #pragma unroll
            for (int r = 0; r < 4; r++) acc[i][j][r] = 0.f;

    for (int k0 = 0; k0 < D_IN; k0 += 32) {
        __syncthreads();
        #pragma unroll
        for (int i = tid; i < 128 * 8; i += 256) {
            int r = i >> 3, c4 = (i & 7) << 2;
            float4 v = *(const float4*)(X + (size_t)r * D_IN + k0 + c4);
            As[r][c4 + 0] = cvt_rna_tf32(v.x); As[r][c4 + 1] = cvt_rna_tf32(v.y);
            As[r][c4 + 2] = cvt_rna_tf32(v.z); As[r][c4 + 3] = cvt_rna_tf32(v.w);
        }
        #pragma unroll
        for (int i = tid; i < 32 * 16; i += 256) {
            int r = i >> 4, c4 = (i & 15) << 2;
            float4 v = *(const float4*)(W + (size_t)(k0 + r) * DKH + c4);
            Bs[r][c4 + 0] = cvt_rna_tf32(v.x); Bs[r][c4 + 1] = cvt_rna_tf32(v.y);
            Bs[r][c4 + 2] = cvt_rna_tf32(v.z); Bs[r][c4 + 3] = cvt_rna_tf32(v.w);
        }
        __syncthreads();

        #pragma unroll
        for (int ks = 0; ks < 4; ks++) {
            const int kk = ks << 3;
            uint32_t a[2][4], bf[4][2];
            #pragma unroll
            for (int mt = 0; mt < 2; mt++) {
                int r = wm + mt * 16 + g;
                a[mt][0] = As[r][kk + tg];     a[mt][1] = As[r + 8][kk + tg];
                a[mt][2] = As[r][kk + tg + 4]; a[mt][3] = As[r + 8][kk + tg + 4];
            }
            #pragma unroll
            for (int nt = 0; nt < 4; nt++) {
                int n = wn + nt * 8 + g;
                bf[nt][0] = Bs[kk + tg][n];
                bf[nt][1] = Bs[kk + tg + 4][n];
            }
            #pragma unroll
            for (int mt = 0; mt < 2; mt++)
                #pragma unroll
                for (int nt = 0; nt < 4; nt++)
                    mma_tf32(acc[mt][nt], a[mt], bf[nt]);
        }
    }

    #pragma unroll
    for (int mt = 0; mt < 2; mt++) {
        #pragma unroll
        for (int nt = 0; nt < 4; nt++) {
            int r = wm + mt * 16 + g;
            int c = wn + nt * 8 + 2 * tg;
            float b0 = bias[c], b1 = bias[c + 1];
            *(float2*)(Out + (size_t)r * DKH + c) =
                make_float2(acc[mt][nt][0] + b0, acc[mt][nt][1] + b1);
            *(float2*)(Out + (size_t)(r + 8) * DKH + c) =
                make_float2(acc[mt][nt][2] + b0, acc[mt][nt][3] + b1);
        }
    }
}

// ============================================================================
// Kernel 2: flash attention on mma.sync tf32.
// Block = 128 threads (4 warps), one (64-query tile, head). KV tiles of 64.
// Each warp owns 16 q-rows. Q fragments cached in registers.
// QPs buffer: Q staging, then reused as warp-private P bands.
// ============================================================================
__global__ __launch_bounds__(128) void attn_tc_kernel()
{
    __shared__ uint32_t QPs[64][68];
    __shared__ uint32_t Ks[64][68];
    __shared__ uint32_t Vs[64][72];

    const int tid = threadIdx.x;
    const int wid = tid >> 5, lane = tid & 31;
    const int g = lane >> 2, tg = lane & 3;
    const int wq = wid * 16;
    const int bh = blockIdx.y;
    const int qtile = blockIdx.x;
    const size_t base = (size_t)bh * S_LEN * DKH;

    const float* Qg = g_Q + base + (size_t)qtile * 64 * DKH;
    const float* Kg = g_K + base;
    const float* Vg = g_V + base;

    // stage Q (64x64) and cache fragments in registers
    #pragma unroll
    for (int i = tid; i < 64 * 16; i += 128) {
        int r = i >> 4, c4 = (i & 15) << 2;
        float4 v = *(const float4*)(Qg + (size_t)r * DKH + c4);
        QPs[r][c4 + 0] = cvt_rna_tf32(v.x); QPs[r][c4 + 1] = cvt_rna_tf32(v.y);
        QPs[r][c4 + 2] = cvt_rna_tf32(v.z); QPs[r][c4 + 3] = cvt_rna_tf32(v.w);
    }
    __syncthreads();
    uint32_t qf[8][4];
    #pragma unroll
    for (int s = 0; s < 8; s++) {
        int kk = s << 3;
        qf[s][0] = QPs[wq + g][kk + tg];     qf[s][1] = QPs[wq + g + 8][kk + tg];
        qf[s][2] = QPs[wq + g][kk + tg + 4]; qf[s][3] = QPs[wq + g + 8][kk + tg + 4];
    }

    float oacc[8][4];
    #pragma unroll
    for (int nt = 0; nt < 8; nt++)
        #pragma unroll
        for (int r = 0; r < 4; r++) oacc[nt][r] = 0.f;
    float m0 = -3.0e38f, m1 = -3.0e38f, l0 = 0.f, l1 = 0.f;

    #pragma unroll 1
    for (int t = 0; t < S_LEN / 64; t++) {
        const float* Kt = Kg + (size_t)t * 64 * DKH;
        const float* Vt = Vg + (size_t)t * 64 * DKH;

        __syncthreads();
        #pragma unroll
        for (int i = tid; i < 64 * 16; i += 128) {
            int r = i >> 4, c4 = (i & 15) << 2;
            float4 kv = *(const float4*)(Kt + (size_t)r * DKH + c4);
            Ks[r][c4 + 0] = cvt_rna_tf32(kv.x); Ks[r][c4 + 1] = cvt_rna_tf32(kv.y);
            Ks[r][c4 + 2] = cvt_rna_tf32(kv.z); Ks[r][c4 + 3] = cvt_rna_tf32(kv.w);
            float4 vv = *(const float4*)(Vt + (size_t)r * DKH + c4);
            Vs[r][c4 + 0] = cvt_rna_tf32(vv.x); Vs[r][c4 + 1] = cvt_rna_tf32(vv.y);
            Vs[r][c4 + 2] = cvt_rna_tf32(vv.z); Vs[r][c4 + 3] = cvt_rna_tf32(vv.w);
        }
        __syncthreads();

        // ---- S = Q K^T : warp computes 16 x 64 scores ----
        float sacc[8][4];
        #pragma unroll
        for (int nt = 0; nt < 8; nt++)
            #pragma unroll
            for (int r = 0; r < 4; r++) sacc[nt][r] = 0.f;
        #pragma unroll
        for (int s = 0; s < 8; s++) {
            const int kk = s << 3;
            uint32_t bf[8][2];
            #pragma unroll
            for (int nt = 0; nt < 8; nt++) {
                int n = nt * 8 + g;             // kv column
                bf[nt][0] = Ks[n][kk + tg];
                bf[nt][1] = Ks[n][kk + tg + 4];
            }
            #pragma unroll
            for (int nt = 0; nt < 8; nt++) mma_tf32(sacc[nt], qf[s], bf[nt]);
        }

        // ---- online softmax (rows owned by lane quads) ----
        float mx0 = -3.0e38f, mx1 = -3.0e38f;
        #pragma unroll
        for (int nt = 0; nt < 8; nt++) {
            mx0 = fmaxf(mx0, fmaxf(sacc[nt][0], sacc[nt][1]));
            mx1 = fmaxf(mx1, fmaxf(sacc[nt][2], sacc[nt][3]));
        }
        mx0 = fmaxf(mx0, __shfl_xor_sync(0xffffffffu, mx0, 1));
        mx0 = fmaxf(mx0, __shfl_xor_sync(0xffffffffu, mx0, 2));
        mx1 = fmaxf(mx1, __shfl_xor_sync(0xffffffffu, mx1, 1));
        mx1 = fmaxf(mx1, __shfl_xor_sync(0xffffffffu, mx1, 2));

        float mn0 = fmaxf(m0, mx0 * 0.125f);
        float mn1 = fmaxf(m1, mx1 * 0.125f);
        float corr0 = __expf(m0 - mn0);
        float corr1 = __expf(m1 - mn1);

        float ps0 = 0.f, ps1 = 0.f;
        #pragma unroll
        for (int nt = 0; nt < 8; nt++) {
            int c = nt * 8 + 2 * tg;
            float p00 = __expf(sacc[nt][0] * 0.125f - mn0);
            float p01 = __expf(sacc[nt][1] * 0.125f - mn0);
            float p10 = __expf(sacc[nt][2] * 0.125f - mn1);
            float p11 = __expf(sacc[nt][3] * 0.125f - mn1);
            ps0 += p00 + p01; ps1 += p10 + p11;
            QPs[wq + g][c]         = cvt_rna_tf32(p00);
            QPs[wq + g][c + 1]     = cvt_rna_tf32(p01);
            QPs[wq + g + 8][c]     = cvt_rna_tf32(p10);
            QPs[wq + g + 8][c + 1] = cvt_rna_tf32(p11);
        }
        ps0 += __shfl_xor_sync(0xffffffffu, ps0, 1);
        ps0 += __shfl_xor_sync(0xffffffffu, ps0, 2);
        ps1 += __shfl_xor_sync(0xffffffffu, ps1, 1);
        ps1 += __shfl_xor_sync(0xffffffffu, ps1, 2);
        l0 = l0 * corr0 + ps0; m0 = mn0;
        l1 = l1 * corr1 + ps1; m1 = mn1;
        __syncwarp();

        // ---- rescale O, then O += P V ----
        #pragma unroll
        for (int nt = 0; nt < 8; nt++) {
            oacc[nt][0] *= corr0; oacc[nt][1] *= corr0;
            oacc[nt][2] *= corr1; oacc[nt][3] *= corr1;
        }
        #pragma unroll
        for (int s = 0; s < 8; s++) {
            const int kk = s << 3;
            uint32_t pa[4];
            pa[0] = QPs[wq + g][kk + tg];     pa[1] = QPs[wq + g + 8][kk + tg];
            pa[2] = QPs[wq + g][kk + tg + 4]; pa[3] = QPs[wq + g + 8][kk + tg + 4];
            uint32_t bf[8][2];
            #pragma unroll
            for (int nt = 0; nt < 8; nt++) {
                int n = nt * 8 + g;             // d column
                bf[nt][0] = Vs[kk + tg][n];
                bf[nt][1] = Vs[kk + tg + 4][n];
            }
            #pragma unroll
            for (int nt = 0; nt < 8; nt++) mma_tf32(oacc[nt], pa, bf[nt]);
        }
        __syncwarp();
    }

    // ---- normalize + write ----
    const float inv0 = 1.f / l0, inv1 = 1.f / l1;
    float* dst0 = g_O + base + ((size_t)qtile * 64 + wq + g) * DKH;
    float* dst1 = g_O + base + ((size_t)qtile * 64 + wq + g + 8) * DKH;
    #pragma unroll
    for (int nt = 0; nt < 8; nt++) {
        int c = nt * 8 + 2 * tg;
        *(float2*)(dst0 + c) = make_float2(oacc[nt][0] * inv0, oacc[nt][1] * inv0);
        *(float2*)(dst1 + c) = make_float2(oacc[nt][2] * inv1, oacc[nt][3] * inv1);
    }
}

// ============================================================================
// Kernel 3: output projection on tensor cores.
// C[4096 x 1024] = O_cat[4096 x 1024] * Wo + bo.
// Same skeleton as kernel 1; A gathered from g_O per-head layout.
// ============================================================================
__global__ __launch_bounds__(256) void out_proj_kernel(
    const float* __restrict__ Wo, const float* __restrict__ bo, float* __restrict__ out)
{
    const int ntile = blockIdx.x;   // 16 tiles of 64 cols
    const int mtile = blockIdx.y;   // 32 tiles of 128 rows

    __shared__ uint32_t As[128][36];
    __shared__ uint32_t Bs[32][72];

    const int tid = threadIdx.x;
    const int wid = tid >> 5, lane = tid & 31;
    const int g = lane >> 2, tg = lane & 3;
    const int wm = (wid >> 1) * 32;
    const int wn = (wid & 1) * 32;

    float acc[2][4][4];
    #pragma unroll
    for (int i = 0; i < 2; i++)
        #pragma unroll
        for (int j = 0; j < 4; j++)
            #pragma unroll
            for (int r = 0; r < 4; r++) acc[i][j][r] = 0.f;

    for (int k0 = 0; k0 < NH * DKH; k0 += 32) {
        const int h = k0 >> 6;   // constant within a 32-chunk
        __syncthreads();
        #pragma unroll
        for (int i = tid; i < 128 * 8; i += 256) {
            int r = i >> 3, c4 = (i & 7) << 2;
            int mrow = mtile * 128 + r;
            int b = mrow >> 11, s = mrow & 2047;
            int col = (k0 & 63) + c4;
            float4 v = *(const float4*)(g_O + (((size_t)(b * NH + h) * S_LEN + s) * DKH + col));
            As[r][c4 + 0] = cvt_rna_tf32(v.x); As[r][c4 + 1] = cvt_rna_tf32(v.y);
            As[r][c4 + 2] = cvt_rna_tf32(v.z); As[r][c4 + 3] = cvt_rna_tf32(v.w);
        }
        #pragma unroll
        for (int i = tid; i < 32 * 16; i += 256) {
            int r = i >> 4, c4 = (i & 15) << 2;
            float4 v = *(const float4*)(Wo + (size_t)(k0 + r) * D_IN + ntile * 64 + c4);
            Bs[r][c4 + 0] = cvt_rna_tf32(v.x); Bs[r][c4 + 1] = cvt_rna_tf32(v.y);
            Bs[r][c4 + 2] = cvt_rna_tf32(v.z); Bs[r][c4 + 3] = cvt_rna_tf32(v.w);
        }
        __syncthreads();

        #pragma unroll
        for (int ks = 0; ks < 4; ks++) {
            const int kk = ks << 3;
            uint32_t a[2][4], bf[4][2];
            #pragma unroll
            for (int mt = 0; mt < 2; mt++) {
                int r = wm + mt * 16 + g;
                a[mt][0] = As[r][kk + tg];     a[mt][1] = As[r + 8][kk + tg];
                a[mt][2] = As[r][kk + tg + 4]; a[mt][3] = As[r + 8][kk + tg + 4];
            }
            #pragma unroll
            for (int nt = 0; nt < 4; nt++) {
                int n = wn + nt * 8 + g;
                bf[nt][0] = Bs[kk + tg][n];
                bf[nt][1] = Bs[kk + tg + 4][n];
            }
            #pragma unroll
            for (int mt = 0; mt < 2; mt++)
                #pragma unroll
                for (int nt = 0; nt < 4; nt++)
                    mma_tf32(acc[mt][nt], a[mt], bf[nt]);
        }
    }

    #pragma unroll
    for (int mt = 0; mt < 2; mt++) {
        #pragma unroll
        for (int nt = 0; nt < 4; nt++) {
            int r = mtile * 128 + wm + mt * 16 + g;
            int c = ntile * 64 + wn + nt * 8 + 2 * tg;
            float b0 = bo[c], b1 = bo[c + 1];
            *(float2*)(out + (size_t)r * D_IN + c) =
                make_float2(acc[mt][nt][0] + b0, acc[mt][nt][1] + b1);
            *(float2*)(out + (size_t)(r + 8) * D_IN + c) =
                make_float2(acc[mt][nt][2] + b0, acc[mt][nt][3] + b1);
        }
    }
}

// ============================================================================
extern "C" void kernel_launch(void* const* d_in, const int* in_sizes, int n_in,
                              void* d_out, int out_size)
{
    (void)in_sizes; (void)n_in; (void)out_size;
    const float* query = (const float*)d_in[0];
    const float* key   = (const float*)d_in[1];
    const float* value = (const float*)d_in[2];
    const float* Wq = (const float*)d_in[3];
    const float* bq = (const float*)d_in[4];
    const float* Wk = (const float*)d_in[5];
    const float* bk = (const float*)d_in[6];
    const float* Wv = (const float*)d_in[7];
    const float* bv = (const float*)d_in[8];
    const float* Wo = (const float*)d_in[9];
    const float* bo = (const float*)d_in[10];

    dim3 g1(S_LEN / 128, B_SZ * NH, 3);
    qkv_proj_kernel<<<g1, 256>>>(query, key, value, Wq, bq, Wk, bk, Wv, bv);

    dim3 g2(S_LEN / 64, B_SZ * NH);
    attn_tc_kernel<<<g2, 128>>>();

    dim3 g3(D_IN / 64, (B_SZ * S_LEN) / 128);
    out_proj_kernel<<<g3, 256>>>(Wo, bo, (float*)d_out);
}